// round 6
// baseline (speedup 1.0000x reference)
#include <cuda_runtime.h>

// Problem constants (fixed by the dataset)
#define BATCH   128
#define IN_DIM  2048
#define HID     2048
#define OUT_DIM 512
#define TSTEPS  32
#define VDECAY  0.5f
#define VTH     0.5f
#define KCHUNK  512   // reference split-K chunk (bit-exact contract from R2)

// ---------------- device scratch (no allocations allowed) ----------------
__device__ float g_xt[TSTEPS * BATCH * IN_DIM];     // [T*B, K] transposed input
__device__ float g_g0[TSTEPS * BATCH * HID];        // layer0 raw GEMM results [T*B, H]
__device__ float g_s0all[TSTEPS * BATCH * HID];     // layer0 spikes per t [T*B, H]
__device__ float g_v1[BATCH * HID];
__device__ float g_s1[BATCH * HID];
__device__ float g_vo[BATCH * OUT_DIM];
__device__ float g_so[BATCH * OUT_DIM];
__device__ float g_p1[4 * BATCH * HID];             // GEMM1 split-K partials
__device__ float g_po[4 * BATCH * OUT_DIM];         // GEMMo split-K partials
__device__ int   g_cnt1[128];                        // per-tile arrival counters (zero-init)
__device__ int   g_cntO[32];

// ---------------- setup: copy initial state, zero output ----------------
__global__ void setup_kernel(const float* __restrict__ h1v, const float* __restrict__ h1s,
                             const float* __restrict__ ov,  const float* __restrict__ os,
                             float* __restrict__ out) {
    int i = blockIdx.x * blockDim.x + threadIdx.x;
    int stride = gridDim.x * blockDim.x;
    for (int idx = i; idx < BATCH * HID; idx += stride) {
        g_v1[idx] = h1v[idx];
        g_s1[idx] = h1s[idx];
    }
    for (int idx = i; idx < BATCH * OUT_DIM; idx += stride) {
        g_vo[idx] = ov[idx];
        g_so[idx] = os[idx];
        out[idx]  = 0.0f;
    }
}

// ---------------- transpose spike_data [B, K, T] -> [T, B, K] ----------------
__global__ void transpose_kernel(const float* __restrict__ sd) {
    __shared__ float tile[32][33];
    int b  = blockIdx.y;
    int k0 = blockIdx.x * 32;
    int tx = threadIdx.x;  // 0..31
    int ty = threadIdx.y;  // 0..7
#pragma unroll
    for (int i = 0; i < 4; i++) {
        int kl = ty + i * 8;
        tile[kl][tx] = sd[(b * IN_DIM + k0 + kl) * TSTEPS + tx];
    }
    __syncthreads();
#pragma unroll
    for (int i = 0; i < 4; i++) {
        int t = ty + i * 8;
        g_xt[(t * BATCH + b) * IN_DIM + k0 + tx] = tile[tx][t];
    }
}

// ---------------- layer0 LIF scan over time (elementwise) ----------------
__global__ void lif0_scan_kernel(const float* __restrict__ h0v, const float* __restrict__ h0s,
                                 const float* __restrict__ b0) {
    int idx = blockIdx.x * blockDim.x + threadIdx.x;
    if (idx >= BATCH * HID) return;
    int h = idx % HID;
    float vv = h0v[idx];
    float ss = h0s[idx];
    float bb = b0[h];
#pragma unroll
    for (int t = 0; t < TSTEPS; t++) {
        float g = g_g0[t * BATCH * HID + idx];
        float decay = __fmul_rn(__fmul_rn(VDECAY, vv), __fadd_rn(1.0f, -ss));
        vv = __fadd_rn(__fadd_rn(decay, g), bb);
        ss = (vv > VTH) ? 1.0f : 0.0f;
        g_s0all[t * BATCH * HID + idx] = ss;
    }
}

// ---------------- double-buffered GEMM tile kernel ----------------
// Rounding contract (bit-exact, from R2): serial in-order FFMA within each
// 512-chunk, chunks folded left-associatively: tot=(((0+c0)+c1)+c2)+c3.
// SPLITK mode: blockIdx.z computes one chunk; partial stored to
// part[z*M*N + m*N + n]. The 4th-arriving CTA per (m0,n0) tile folds all 4
// partials in z order, applies the LIF epilogue (writes v,s; out += s if ACC),
// and resets the tile counter. Non-SPLITK: full K in-kernel fold, raw store.
template <int M, int N, int KTOT, int BM, int BN, int TM, int TN, int THREADS,
          bool SPLITK, bool ACC>
__global__ __launch_bounds__(THREADS) void gemm_kernel(
    const float* __restrict__ X,
    const float* __restrict__ W,
    float* __restrict__ part,       // SPLITK: partial buffer; else: raw output
    const float* __restrict__ bias, // SPLITK fold only
    float* __restrict__ v,
    float* __restrict__ s,
    float* __restrict__ out,
    int* __restrict__ cnt)
{
    constexpr int BK  = 16;
    constexpr int KLOC = SPLITK ? KCHUNK : KTOT;
    constexpr int NT  = KLOC / BK;
    constexpr int CH  = KCHUNK / BK;       // tiles per rounding chunk (32)
    constexpr int XLD = BM * BK / THREADS;
    constexpr int WLD = BN * BK / THREADS;
    constexpr int RS  = THREADS / BK;

    __shared__ __align__(16) float Xs[2][BK][BM + 4];
    __shared__ __align__(16) float Ws[2][BK][BN + 4];

    const int tid = threadIdx.x;
    const int m0 = blockIdx.y * BM;
    const int n0 = blockIdx.x * BN;
    const int kbase = SPLITK ? blockIdx.z * KCHUNK : 0;

    const int lk = tid % BK;
    const int lr = tid / BK;
    const float* Xp = X + (size_t)(m0 + lr) * KTOT + kbase + lk;
    const float* Wp = W + (size_t)(n0 + lr) * KTOT + kbase + lk;

    const int tx = tid % (BN / TN);
    const int ty = tid / (BN / TN);

    float xr[XLD], wr[WLD];
    float acc[TM][TN], tot[TM][TN];
#pragma unroll
    for (int i = 0; i < TM; i++)
#pragma unroll
        for (int j = 0; j < TN; j++) { acc[i][j] = 0.0f; tot[i][j] = 0.0f; }

    // prologue: tile0 -> regs -> buf0 ; tile1 -> regs (in flight)
#pragma unroll
    for (int i = 0; i < XLD; i++) xr[i] = Xp[(size_t)i * RS * KTOT];
#pragma unroll
    for (int i = 0; i < WLD; i++) wr[i] = Wp[(size_t)i * RS * KTOT];
#pragma unroll
    for (int i = 0; i < XLD; i++) Xs[0][lk][lr + i * RS] = xr[i];
#pragma unroll
    for (int i = 0; i < WLD; i++) Ws[0][lk][lr + i * RS] = wr[i];
#pragma unroll
    for (int i = 0; i < XLD; i++) xr[i] = Xp[(size_t)i * RS * KTOT + BK];
#pragma unroll
    for (int i = 0; i < WLD; i++) wr[i] = Wp[(size_t)i * RS * KTOT + BK];
    __syncthreads();

    for (int t = 0; t < NT; t++) {
        const int cur = t & 1;
        if (t + 1 < NT) {
#pragma unroll
            for (int i = 0; i < XLD; i++) Xs[cur ^ 1][lk][lr + i * RS] = xr[i];
#pragma unroll
            for (int i = 0; i < WLD; i++) Ws[cur ^ 1][lk][lr + i * RS] = wr[i];
        }
        if (t + 2 < NT) {
#pragma unroll
            for (int i = 0; i < XLD; i++) xr[i] = Xp[(size_t)i * RS * KTOT + (t + 2) * BK];
#pragma unroll
            for (int i = 0; i < WLD; i++) wr[i] = Wp[(size_t)i * RS * KTOT + (t + 2) * BK];
        }

#pragma unroll
        for (int kk = 0; kk < BK; kk++) {
            float a[TM], b[TN];
            float4 av = *reinterpret_cast<const float4*>(&Xs[cur][kk][ty * TM]);
            a[0] = av.x; a[1] = av.y; a[2] = av.z; a[3] = av.w;
            float4 bv = *reinterpret_cast<const float4*>(&Ws[cur][kk][tx * TN]);
            b[0] = bv.x; b[1] = bv.y; b[2] = bv.z; b[3] = bv.w;
#pragma unroll
            for (int i = 0; i < TM; i++)
#pragma unroll
                for (int j = 0; j < TN; j++)
                    acc[i][j] = __fmaf_rn(a[i], b[j], acc[i][j]);
        }

        if ((t & (CH - 1)) == (CH - 1)) {
#pragma unroll
            for (int i = 0; i < TM; i++)
#pragma unroll
                for (int j = 0; j < TN; j++) {
                    tot[i][j] = __fadd_rn(tot[i][j], acc[i][j]);
                    acc[i][j] = 0.0f;
                }
        }
        __syncthreads();
    }

    if (!SPLITK) {
        // raw store of fully-folded result
#pragma unroll
        for (int i = 0; i < TM; i++) {
            int m = m0 + ty * TM + i;
#pragma unroll
            for (int j = 0; j < TN; j++) {
                int n = n0 + tx * TN + j;
                part[(size_t)m * N + n] = tot[i][j];
            }
        }
        return;
    }

    // ---- SPLITK: store this chunk's partial ----
    const size_t MN = (size_t)M * N;
    const size_t zoff = (size_t)blockIdx.z * MN;
#pragma unroll
    for (int i = 0; i < TM; i++) {
        int m = m0 + ty * TM + i;
#pragma unroll
        for (int j = 0; j < TN; j++) {
            int n = n0 + tx * TN + j;
            part[zoff + (size_t)m * N + n] = tot[i][j];
        }
    }

    // ---- arrival counter: 4th CTA per (m0,n0) tile performs the fold ----
    __threadfence();                       // release partials
    __shared__ int s_old;
    const int tileId = blockIdx.y * gridDim.x + blockIdx.x;
    if (tid == 0) s_old = atomicAdd(&cnt[tileId], 1);
    __syncthreads();
    if (s_old != 3) return;

    if (tid == 0) cnt[tileId] = 0;         // reset for next launch
    __threadfence();                       // acquire partials from peer CTAs

#pragma unroll
    for (int i = 0; i < TM; i++) {
        int m = m0 + ty * TM + i;
#pragma unroll
        for (int j = 0; j < TN; j++) {
            int n = n0 + tx * TN + j;
            size_t idx = (size_t)m * N + n;
            float f = 0.0f;
            f = __fadd_rn(f, part[idx]);
            f = __fadd_rn(f, part[MN + idx]);
            f = __fadd_rn(f, part[2 * MN + idx]);
            f = __fadd_rn(f, part[3 * MN + idx]);
            float decay = __fmul_rn(__fmul_rn(VDECAY, v[idx]), __fadd_rn(1.0f, -s[idx]));
            float vv = __fadd_rn(__fadd_rn(decay, f), bias[n]);
            float ss = (vv > VTH) ? 1.0f : 0.0f;
            v[idx] = vv;
            s[idx] = ss;
            if (ACC) out[idx] += ss;
        }
    }
}

// ---------------- launcher ----------------
extern "C" void kernel_launch(void* const* d_in, const int* in_sizes, int n_in,
                              void* d_out, int out_size) {
    (void)in_sizes; (void)n_in; (void)out_size;
    const float* sd  = (const float*)d_in[0];
    const float* h0v = (const float*)d_in[1];
    const float* h0s = (const float*)d_in[2];
    const float* h1v = (const float*)d_in[3];
    const float* h1s = (const float*)d_in[4];
    const float* ov  = (const float*)d_in[5];
    const float* os  = (const float*)d_in[6];
    const float* W0  = (const float*)d_in[7];
    const float* b0  = (const float*)d_in[8];
    const float* W1  = (const float*)d_in[9];
    const float* b1  = (const float*)d_in[10];
    const float* Wo  = (const float*)d_in[11];
    const float* bo  = (const float*)d_in[12];
    float* out = (float*)d_out;

    float *xt, *gg0, *s0all, *v1, *s1, *vo, *so, *p1, *po;
    int *cnt1, *cntO;
    cudaGetSymbolAddress((void**)&xt,    g_xt);
    cudaGetSymbolAddress((void**)&gg0,   g_g0);
    cudaGetSymbolAddress((void**)&s0all, g_s0all);
    cudaGetSymbolAddress((void**)&v1,    g_v1);
    cudaGetSymbolAddress((void**)&s1,    g_s1);
    cudaGetSymbolAddress((void**)&vo,    g_vo);
    cudaGetSymbolAddress((void**)&so,    g_so);
    cudaGetSymbolAddress((void**)&p1,    g_p1);
    cudaGetSymbolAddress((void**)&po,    g_po);
    cudaGetSymbolAddress((void**)&cnt1,  g_cnt1);
    cudaGetSymbolAddress((void**)&cntO,  g_cntO);

    setup_kernel<<<512, 256>>>(h1v, h1s, ov, os, out);

    dim3 tb(32, 8);
    dim3 tg(IN_DIM / 32, BATCH);
    transpose_kernel<<<tg, tb>>>(sd);

    // Layer0 batched over all timesteps: M = T*B = 4096, full K in-kernel fold.
    {
        dim3 grid(HID / 64, (TSTEPS * BATCH) / 32);   // 4096 CTAs
        gemm_kernel<TSTEPS * BATCH, HID, IN_DIM, 32, 64, 4, 4, 128, false, false>
            <<<grid, 128>>>(xt, W0, gg0, nullptr, nullptr, nullptr, nullptr, nullptr);
    }

    // Layer0 LIF recurrence (elementwise scan over T)
    lif0_scan_kernel<<<(BATCH * HID + 255) / 256, 256>>>(h0v, h0s, b0);

    dim3 grid1(HID / 64, BATCH / 32, 4);      // (32,4,4) = 512 CTAs, 128 tiles
    dim3 gridO(OUT_DIM / 64, BATCH / 32, 4);  // (8,4,4)  = 128 CTAs, 32 tiles

    for (int t = 0; t < TSTEPS; t++) {
        gemm_kernel<BATCH, HID, HID, 32, 64, 4, 4, 128, true, false><<<grid1, 128>>>(
            s0all + (size_t)t * BATCH * HID, W1, p1, b1, v1, s1, nullptr, cnt1);
        gemm_kernel<BATCH, OUT_DIM, HID, 32, 64, 4, 4, 128, true, true><<<gridO, 128>>>(
            s1, Wo, po, bo, vo, so, out, cntO);
    }
}

// round 7
// speedup vs baseline: 1.4011x; 1.4011x over previous
#include <cuda_runtime.h>

// Problem constants (fixed by the dataset)
#define BATCH   128
#define IN_DIM  2048
#define HID     2048
#define OUT_DIM 512
#define TSTEPS  32
#define VDECAY  0.5f
#define VTH     0.5f
#define KCHUNK  512   // reference split-K chunk (bit-exact contract from R2)

#define TB (TSTEPS * BATCH)   // 4096 batched rows

// ---------------- device scratch (no allocations allowed) ----------------
__device__ float g_xt[TB * IN_DIM];      // [T*B, K] transposed input
__device__ float g_g0[TB * HID];         // layer0 raw GEMM results
__device__ float g_s0all[TB * HID];      // layer0 spikes per t
__device__ float g_g1[TB * HID];         // layer1 raw GEMM results
__device__ float g_s1all[TB * HID];      // layer1 spikes per t
__device__ float g_go[TB * OUT_DIM];     // output-layer raw GEMM results

// ---------------- transpose spike_data [B, K, T] -> [T, B, K] ----------------
__global__ void transpose_kernel(const float* __restrict__ sd) {
    __shared__ float tile[32][33];
    int b  = blockIdx.y;
    int k0 = blockIdx.x * 32;
    int tx = threadIdx.x;  // 0..31
    int ty = threadIdx.y;  // 0..7
#pragma unroll
    for (int i = 0; i < 4; i++) {
        int kl = ty + i * 8;
        tile[kl][tx] = sd[(b * IN_DIM + k0 + kl) * TSTEPS + tx];
    }
    __syncthreads();
#pragma unroll
    for (int i = 0; i < 4; i++) {
        int t = ty + i * 8;
        g_xt[(t * BATCH + b) * IN_DIM + k0 + tx] = tile[tx][t];
    }
}

// ---------------- LIF scan over time (elementwise, hidden layers) ----------------
// v = (0.5*v*(1-s) + gemm) + bias ; s = (v > VTH). Rounding matches reference.
template <int N>
__global__ void lif_scan_kernel(const float* __restrict__ gin,   // [T, B*N]
                                float* __restrict__ sall,        // [T, B*N]
                                const float* __restrict__ v0in,
                                const float* __restrict__ s0in,
                                const float* __restrict__ bias) {
    int idx = blockIdx.x * blockDim.x + threadIdx.x;
    if (idx >= BATCH * N) return;
    float vv = v0in[idx];
    float ss = s0in[idx];
    float bb = bias[idx % N];
#pragma unroll
    for (int t = 0; t < TSTEPS; t++) {
        float g = gin[(size_t)t * BATCH * N + idx];
        float decay = __fmul_rn(__fmul_rn(VDECAY, vv), __fadd_rn(1.0f, -ss));
        vv = __fadd_rn(__fadd_rn(decay, g), bb);
        ss = (vv > VTH) ? 1.0f : 0.0f;
        sall[(size_t)t * BATCH * N + idx] = ss;
    }
}

// ---------------- output-layer LIF scan: accumulate spike counts ----------------
__global__ void lifo_scan_kernel(const float* __restrict__ gin,   // [T, B*OUT]
                                 const float* __restrict__ v0in,
                                 const float* __restrict__ s0in,
                                 const float* __restrict__ bias,
                                 float* __restrict__ out) {
    int idx = blockIdx.x * blockDim.x + threadIdx.x;
    if (idx >= BATCH * OUT_DIM) return;
    float vv = v0in[idx];
    float ss = s0in[idx];
    float bb = bias[idx % OUT_DIM];
    float acc = 0.0f;
#pragma unroll
    for (int t = 0; t < TSTEPS; t++) {
        float g = gin[(size_t)t * BATCH * OUT_DIM + idx];
        float decay = __fmul_rn(__fmul_rn(VDECAY, vv), __fadd_rn(1.0f, -ss));
        vv = __fadd_rn(__fadd_rn(decay, g), bb);
        ss = (vv > VTH) ? 1.0f : 0.0f;
        acc += ss;
    }
    out[idx] = acc;
}

// ---------------- double-buffered GEMM tile kernel (full K) ----------------
// Rounding contract (bit-exact since R2): serial in-order FFMA within each
// 512-chunk, chunks folded left-associatively: tot=(((0+c0)+c1)+c2)+c3.
// Stores raw folded sums to out[m*N + n].
template <int N, int KTOT, int BM, int BN, int TM, int TN, int THREADS>
__global__ __launch_bounds__(THREADS) void gemm_kernel(
    const float* __restrict__ X,
    const float* __restrict__ W,
    float* __restrict__ out)
{
    constexpr int BK  = 16;
    constexpr int NT  = KTOT / BK;
    constexpr int CH  = KCHUNK / BK;       // tiles per rounding chunk (32)
    constexpr int XLD = BM * BK / THREADS;
    constexpr int WLD = BN * BK / THREADS;
    constexpr int RS  = THREADS / BK;

    __shared__ __align__(16) float Xs[2][BK][BM + 4];
    __shared__ __align__(16) float Ws[2][BK][BN + 4];

    const int tid = threadIdx.x;
    const int m0 = blockIdx.y * BM;
    const int n0 = blockIdx.x * BN;

    const int lk = tid % BK;
    const int lr = tid / BK;
    const float* Xp = X + (size_t)(m0 + lr) * KTOT + lk;
    const float* Wp = W + (size_t)(n0 + lr) * KTOT + lk;

    const int tx = tid % (BN / TN);
    const int ty = tid / (BN / TN);

    float xr[XLD], wr[WLD];
    float acc[TM][TN], tot[TM][TN];
#pragma unroll
    for (int i = 0; i < TM; i++)
#pragma unroll
        for (int j = 0; j < TN; j++) { acc[i][j] = 0.0f; tot[i][j] = 0.0f; }

    // prologue: tile0 -> regs -> buf0 ; tile1 -> regs (in flight)
#pragma unroll
    for (int i = 0; i < XLD; i++) xr[i] = Xp[(size_t)i * RS * KTOT];
#pragma unroll
    for (int i = 0; i < WLD; i++) wr[i] = Wp[(size_t)i * RS * KTOT];
#pragma unroll
    for (int i = 0; i < XLD; i++) Xs[0][lk][lr + i * RS] = xr[i];
#pragma unroll
    for (int i = 0; i < WLD; i++) Ws[0][lk][lr + i * RS] = wr[i];
#pragma unroll
    for (int i = 0; i < XLD; i++) xr[i] = Xp[(size_t)i * RS * KTOT + BK];
#pragma unroll
    for (int i = 0; i < WLD; i++) wr[i] = Wp[(size_t)i * RS * KTOT + BK];
    __syncthreads();

    for (int t = 0; t < NT; t++) {
        const int cur = t & 1;
        if (t + 1 < NT) {
#pragma unroll
            for (int i = 0; i < XLD; i++) Xs[cur ^ 1][lk][lr + i * RS] = xr[i];
#pragma unroll
            for (int i = 0; i < WLD; i++) Ws[cur ^ 1][lk][lr + i * RS] = wr[i];
        }
        if (t + 2 < NT) {
#pragma unroll
            for (int i = 0; i < XLD; i++) xr[i] = Xp[(size_t)i * RS * KTOT + (t + 2) * BK];
#pragma unroll
            for (int i = 0; i < WLD; i++) wr[i] = Wp[(size_t)i * RS * KTOT + (t + 2) * BK];
        }

#pragma unroll
        for (int kk = 0; kk < BK; kk++) {
            float a[TM], b[TN];
            float4 av = *reinterpret_cast<const float4*>(&Xs[cur][kk][ty * TM]);
            a[0] = av.x; a[1] = av.y; a[2] = av.z; a[3] = av.w;
            float4 bv = *reinterpret_cast<const float4*>(&Ws[cur][kk][tx * TN]);
            b[0] = bv.x; b[1] = bv.y; b[2] = bv.z; b[3] = bv.w;
#pragma unroll
            for (int i = 0; i < TM; i++)
#pragma unroll
                for (int j = 0; j < TN; j++)
                    acc[i][j] = __fmaf_rn(a[i], b[j], acc[i][j]);
        }

        if ((t & (CH - 1)) == (CH - 1)) {
#pragma unroll
            for (int i = 0; i < TM; i++)
#pragma unroll
                for (int j = 0; j < TN; j++) {
                    tot[i][j] = __fadd_rn(tot[i][j], acc[i][j]);
                    acc[i][j] = 0.0f;
                }
        }
        __syncthreads();
    }

    // epilogue: raw store of folded sums
#pragma unroll
    for (int i = 0; i < TM; i++) {
        int m = m0 + ty * TM + i;
#pragma unroll
        for (int j = 0; j < TN; j++) {
            int n = n0 + tx * TN + j;
            out[(size_t)m * N + n] = tot[i][j];
        }
    }
}

// ---------------- launcher ----------------
extern "C" void kernel_launch(void* const* d_in, const int* in_sizes, int n_in,
                              void* d_out, int out_size) {
    (void)in_sizes; (void)n_in; (void)out_size;
    const float* sd  = (const float*)d_in[0];
    const float* h0v = (const float*)d_in[1];
    const float* h0s = (const float*)d_in[2];
    const float* h1v = (const float*)d_in[3];
    const float* h1s = (const float*)d_in[4];
    const float* ov  = (const float*)d_in[5];
    const float* os  = (const float*)d_in[6];
    const float* W0  = (const float*)d_in[7];
    const float* b0  = (const float*)d_in[8];
    const float* W1  = (const float*)d_in[9];
    const float* b1  = (const float*)d_in[10];
    const float* Wo  = (const float*)d_in[11];
    const float* bo  = (const float*)d_in[12];
    float* out = (float*)d_out;

    float *xt, *gg0, *s0all, *gg1, *s1all, *ggo;
    cudaGetSymbolAddress((void**)&xt,    g_xt);
    cudaGetSymbolAddress((void**)&gg0,   g_g0);
    cudaGetSymbolAddress((void**)&s0all, g_s0all);
    cudaGetSymbolAddress((void**)&gg1,   g_g1);
    cudaGetSymbolAddress((void**)&s1all, g_s1all);
    cudaGetSymbolAddress((void**)&ggo,   g_go);

    // 1) transpose input [B,K,T] -> [T,B,K]
    dim3 tb(32, 8);
    dim3 tg(IN_DIM / 32, BATCH);
    transpose_kernel<<<tg, tb>>>(sd);

    // 2) layer0 GEMM batched over all timesteps (M = T*B = 4096)
    {
        dim3 grid(HID / 64, TB / 32);   // (32, 128) = 4096 CTAs
        gemm_kernel<HID, IN_DIM, 32, 64, 4, 4, 128><<<grid, 128>>>(xt, W0, gg0);
    }

    // 3) layer0 LIF recurrence scan
    lif_scan_kernel<HID><<<(BATCH * HID + 255) / 256, 256>>>(gg0, s0all, h0v, h0s, b0);

    // 4) layer1 GEMM batched over all timesteps
    {
        dim3 grid(HID / 64, TB / 32);   // 4096 CTAs
        gemm_kernel<HID, HID, 32, 64, 4, 4, 128><<<grid, 128>>>(s0all, W1, gg1);
    }

    // 5) layer1 LIF recurrence scan
    lif_scan_kernel<HID><<<(BATCH * HID + 255) / 256, 256>>>(gg1, s1all, h1v, h1s, b1);

    // 6) output-layer GEMM batched over all timesteps
    {
        dim3 grid(OUT_DIM / 64, TB / 32);   // (8, 128) = 1024 CTAs
        gemm_kernel<OUT_DIM, HID, 32, 64, 4, 4, 128><<<grid, 128>>>(s1all, Wo, ggo);
    }

    // 7) output-layer LIF scan + spike-count accumulation
    lifo_scan_kernel<<<(BATCH * OUT_DIM + 255) / 256, 256>>>(ggo, ov, os, bo, out);
}

// round 9
// speedup vs baseline: 1.5449x; 1.1026x over previous
#include <cuda_runtime.h>
#include <cstdint>

// Problem constants (fixed by the dataset)
#define BATCH   128
#define IN_DIM  2048
#define HID     2048
#define OUT_DIM 512
#define TSTEPS  32
#define VDECAY  0.5f
#define VTH     0.5f
#define KCHUNK  512   // reference split-K chunk (bit-exact contract from R2)

#define TB (TSTEPS * BATCH)   // 4096 batched rows

// ---------------- device scratch (no allocations allowed) ----------------
__device__ float g_xt[TB * IN_DIM];      // [T*B, K] transposed input
__device__ float g_g0[TB * HID];         // layer0 raw GEMM results
__device__ float g_s0all[TB * HID];      // layer0 spikes per t
__device__ float g_g1[TB * HID];         // layer1 raw GEMM results
__device__ float g_s1all[TB * HID];      // layer1 spikes per t
__device__ float g_go[TB * OUT_DIM];     // output-layer raw GEMM results

// packed f32x2 FMA: two independent IEEE-RN FMAs (lo,hi) -> per-element
// rounding identical to scalar FFMA chains.
#define FMA2(accv, av, wv) \
    asm("fma.rn.f32x2 %0, %1, %2, %0;" : "+l"(accv) : "l"(av), "l"(wv))
#define ADD2(totv, accv) \
    asm("add.rn.f32x2 %0, %0, %1;" : "+l"(totv) : "l"(accv))
#define DUP2(dst, fval) \
    asm("mov.b64 %0, {%1, %1};" : "=l"(dst) : "r"(__float_as_uint(fval)))

// ---------------- transpose spike_data [B, K, T] -> [T, B, K] ----------------
__global__ void transpose_kernel(const float* __restrict__ sd) {
    __shared__ float tile[32][33];
    int b  = blockIdx.y;
    int k0 = blockIdx.x * 32;
    int tx = threadIdx.x;
    int ty = threadIdx.y;
#pragma unroll
    for (int i = 0; i < 4; i++) {
        int kl = ty + i * 8;
        tile[kl][tx] = sd[(b * IN_DIM + k0 + kl) * TSTEPS + tx];
    }
    __syncthreads();
#pragma unroll
    for (int i = 0; i < 4; i++) {
        int t = ty + i * 8;
        g_xt[(t * BATCH + b) * IN_DIM + k0 + tx] = tile[tx][t];
    }
}

// ---------------- LIF scan over time (elementwise, hidden layers) ----------------
template <int N>
__global__ void lif_scan_kernel(const float* __restrict__ gin,   // [T, B*N]
                                float* __restrict__ sall,        // [T, B*N]
                                const float* __restrict__ v0in,
                                const float* __restrict__ s0in,
                                const float* __restrict__ bias) {
    int idx = blockIdx.x * blockDim.x + threadIdx.x;
    if (idx >= BATCH * N) return;
    float vv = v0in[idx];
    float ss = s0in[idx];
    float bb = bias[idx % N];
#pragma unroll
    for (int t = 0; t < TSTEPS; t++) {
        float g = gin[(size_t)t * BATCH * N + idx];
        float decay = __fmul_rn(__fmul_rn(VDECAY, vv), __fadd_rn(1.0f, -ss));
        vv = __fadd_rn(__fadd_rn(decay, g), bb);
        ss = (vv > VTH) ? 1.0f : 0.0f;
        sall[(size_t)t * BATCH * N + idx] = ss;
    }
}

// ---------------- output-layer LIF scan: accumulate spike counts ----------------
__global__ void lifo_scan_kernel(const float* __restrict__ gin,
                                 const float* __restrict__ v0in,
                                 const float* __restrict__ s0in,
                                 const float* __restrict__ bias,
                                 float* __restrict__ out) {
    int idx = blockIdx.x * blockDim.x + threadIdx.x;
    if (idx >= BATCH * OUT_DIM) return;
    float vv = v0in[idx];
    float ss = s0in[idx];
    float bb = bias[idx % OUT_DIM];
    float acc = 0.0f;
#pragma unroll
    for (int t = 0; t < TSTEPS; t++) {
        float g = gin[(size_t)t * BATCH * OUT_DIM + idx];
        float decay = __fmul_rn(__fmul_rn(VDECAY, vv), __fadd_rn(1.0f, -ss));
        vv = __fadd_rn(__fadd_rn(decay, g), bb);
        ss = (vv > VTH) ? 1.0f : 0.0f;
        acc += ss;
    }
    out[idx] = acc;
}

// ---------------- double-buffered GEMM, packed f32x2 accumulation ----------------
// C[m][n] = sum_k X[m][k]*W[n][k]. Rounding contract (bit-exact since R2):
// serial in-order FMA per element within each 512-chunk, chunks folded
// left-associatively. fma.rn.f32x2 = two independent IEEE-RN FMAs, so each
// output element's chain is identical to the scalar version.
// Tiles: BM=32, BN=128, 128 threads; thread tile TM=4 rows x TN=8 cols
// (cols tx*4..+3 and 64+tx*4..+3 -> 16B LDS stride, conflict-free).
template <int N, int KTOT>
__global__ __launch_bounds__(128) void gemm_kernel(
    const float* __restrict__ X,
    const float* __restrict__ W,
    float* __restrict__ out)
{
    constexpr int BK  = 16;
    constexpr int BM  = 32;
    constexpr int BN  = 128;
    constexpr int NT  = KTOT / BK;
    constexpr int CH  = KCHUNK / BK;       // 32 tiles per rounding chunk
    constexpr int XLD = BM * BK / 128;     // 4
    constexpr int WLD = BN * BK / 128;     // 16
    constexpr int RS  = 128 / BK;          // 8

    __shared__ __align__(16) float Xs[2][BK][BM + 4];
    __shared__ __align__(16) float Ws[2][BK][BN + 4];

    const int tid = threadIdx.x;
    const int m0 = blockIdx.y * BM;
    const int n0 = blockIdx.x * BN;

    const int lk = tid % BK;
    const int lr = tid / BK;               // 0..7
    const float* Xp = X + (size_t)(m0 + lr) * KTOT + lk;
    const float* Wp = W + (size_t)(n0 + lr) * KTOT + lk;

    const int tx = tid % 16;               // column group
    const int ty = tid / 16;               // 0..7 -> rows ty*4..ty*4+3

    float xr[XLD], wr[WLD];
    // acc[i][j]: row ty*4+i ; j=0,1 -> cols tx*4+{0,1},{2,3} ; j=2,3 -> 64+tx*4+{0,1},{2,3}
    unsigned long long acc[4][4], tot[4][4];
#pragma unroll
    for (int i = 0; i < 4; i++)
#pragma unroll
        for (int j = 0; j < 4; j++) { acc[i][j] = 0ull; tot[i][j] = 0ull; }

    // prologue: tile0 -> regs -> buf0 ; tile1 -> regs (in flight)
#pragma unroll
    for (int i = 0; i < XLD; i++) xr[i] = Xp[(size_t)i * RS * KTOT];
#pragma unroll
    for (int i = 0; i < WLD; i++) wr[i] = Wp[(size_t)i * RS * KTOT];
#pragma unroll
    for (int i = 0; i < XLD; i++) Xs[0][lk][lr + i * RS] = xr[i];
#pragma unroll
    for (int i = 0; i < WLD; i++) Ws[0][lk][lr + i * RS] = wr[i];
#pragma unroll
    for (int i = 0; i < XLD; i++) xr[i] = Xp[(size_t)i * RS * KTOT + BK];
#pragma unroll
    for (int i = 0; i < WLD; i++) wr[i] = Wp[(size_t)i * RS * KTOT + BK];
    __syncthreads();

    for (int t = 0; t < NT; t++) {
        const int cur = t & 1;
        if (t + 1 < NT) {
#pragma unroll
            for (int i = 0; i < XLD; i++) Xs[cur ^ 1][lk][lr + i * RS] = xr[i];
#pragma unroll
            for (int i = 0; i < WLD; i++) Ws[cur ^ 1][lk][lr + i * RS] = wr[i];
        }
        if (t + 2 < NT) {
#pragma unroll
            for (int i = 0; i < XLD; i++) xr[i] = Xp[(size_t)i * RS * KTOT + (t + 2) * BK];
#pragma unroll
            for (int i = 0; i < WLD; i++) wr[i] = Wp[(size_t)i * RS * KTOT + (t + 2) * BK];
        }

#pragma unroll
        for (int kk = 0; kk < BK; kk++) {
            float4 av = *reinterpret_cast<const float4*>(&Xs[cur][kk][ty * 4]);
            unsigned long long aa[4];
            DUP2(aa[0], av.x);
            DUP2(aa[1], av.y);
            DUP2(aa[2], av.z);
            DUP2(aa[3], av.w);
            const float* wrow = &Ws[cur][kk][0];
            ulonglong2 wA = *reinterpret_cast<const ulonglong2*>(wrow + tx * 4);
            ulonglong2 wB = *reinterpret_cast<const ulonglong2*>(wrow + 64 + tx * 4);
#pragma unroll
            for (int i = 0; i < 4; i++) {
                FMA2(acc[i][0], aa[i], wA.x);
                FMA2(acc[i][1], aa[i], wA.y);
                FMA2(acc[i][2], aa[i], wB.x);
                FMA2(acc[i][3], aa[i], wB.y);
            }
        }

        if ((t & (CH - 1)) == (CH - 1)) {
            // fold chunk (left-associative per lane), reset chunk accumulator
#pragma unroll
            for (int i = 0; i < 4; i++)
#pragma unroll
                for (int j = 0; j < 4; j++) {
                    ADD2(tot[i][j], acc[i][j]);
                    acc[i][j] = 0ull;
                }
        }
        __syncthreads();
    }

    // epilogue: raw store of folded sums
#pragma unroll
    for (int i = 0; i < 4; i++) {
        float* orow = out + (size_t)(m0 + ty * 4 + i) * N + n0;
#pragma unroll
        for (int j = 0; j < 4; j++) {
            float2 f2;
            f2.x = __uint_as_float((uint32_t)(tot[i][j] & 0xFFFFFFFFull));
            f2.y = __uint_as_float((uint32_t)(tot[i][j] >> 32));
            int col = (j < 2) ? (tx * 4 + 2 * j) : (64 + tx * 4 + 2 * (j - 2));
            *reinterpret_cast<float2*>(orow + col) = f2;
        }
    }
}

// ---------------- launcher ----------------
extern "C" void kernel_launch(void* const* d_in, const int* in_sizes, int n_in,
                              void* d_out, int out_size) {
    (void)in_sizes; (void)n_in; (void)out_size;
    const float* sd  = (const float*)d_in[0];
    const float* h0v = (const float*)d_in[1];
    const float* h0s = (const float*)d_in[2];
    const float* h1v = (const float*)d_in[3];
    const float* h1s = (const float*)d_in[4];
    const float* ov  = (const float*)d_in[5];
    const float* os  = (const float*)d_in[6];
    const float* W0  = (const float*)d_in[7];
    const float* b0  = (const float*)d_in[8];
    const float* W1  = (const float*)d_in[9];
    const float* b1  = (const float*)d_in[10];
    const float* Wo  = (const float*)d_in[11];
    const float* bo  = (const float*)d_in[12];
    float* out = (float*)d_out;

    float *xt, *gg0, *s0all, *gg1, *s1all, *ggo;
    cudaGetSymbolAddress((void**)&xt,    g_xt);
    cudaGetSymbolAddress((void**)&gg0,   g_g0);
    cudaGetSymbolAddress((void**)&s0all, g_s0all);
    cudaGetSymbolAddress((void**)&gg1,   g_g1);
    cudaGetSymbolAddress((void**)&s1all, g_s1all);
    cudaGetSymbolAddress((void**)&ggo,   g_go);

    // 1) transpose input [B,K,T] -> [T,B,K]
    {
        dim3 tb(32, 8);
        dim3 tg(IN_DIM / 32, BATCH);
        transpose_kernel<<<tg, tb>>>(sd);
    }

    // 2) layer0 GEMM batched over all timesteps (M = T*B = 4096)
    {
        dim3 grid(HID / 128, TB / 32);   // (16, 128) = 2048 CTAs
        gemm_kernel<HID, IN_DIM><<<grid, 128>>>(xt, W0, gg0);
    }

    // 3) layer0 LIF scan
    lif_scan_kernel<HID><<<(BATCH * HID + 255) / 256, 256>>>(gg0, s0all, h0v, h0s, b0);

    // 4) layer1 GEMM
    {
        dim3 grid(HID / 128, TB / 32);
        gemm_kernel<HID, HID><<<grid, 128>>>(s0all, W1, gg1);
    }

    // 5) layer1 LIF scan
    lif_scan_kernel<HID><<<(BATCH * HID + 255) / 256, 256>>>(gg1, s1all, h1v, h1s, b1);

    // 6) output-layer GEMM
    {
        dim3 grid(OUT_DIM / 128, TB / 32);   // (4, 128) = 512 CTAs
        gemm_kernel<OUT_DIM, HID><<<grid, 128>>>(s1all, Wo, ggo);
    }

    // 7) output LIF scan + spike-count accumulation
    lifo_scan_kernel<<<(BATCH * OUT_DIM + 255) / 256, 256>>>(ggo, ov, os, bo, out);
}